// round 6
// baseline (speedup 1.0000x reference)
#include <cuda_runtime.h>
#include <cstdint>

#define SEQ   8192
#define DIM   256
#define HID   1024
#define KCB   512
#define NCLS  50
#define NCTA  128
#define TPB   256
#define UPC   8        // hidden units per CTA = HID / NCTA

// ---------------- device-global scratch (no allocations allowed) -------------
__device__ int      g_idx[SEQ];
// h publish buffer: slot s holds h(s), one {f32 bits, gen tag} per unit. 67 MB.
__device__ uint2    g_hpub[(SEQ + 1) * HID];
// W_ih transposed+permuted: [k][cta*32 + unit*4 + gate]. 8 MB.
__device__ float    g_wih_t[KCB * 4 * HID];
__device__ unsigned g_run = 0;   // generation counter, bumped once per launch

// ---------------- accurate-enough activations (fast-math independent) --------
__device__ __forceinline__ float sigm(float x) {
    return 1.0f / (1.0f + __expf(-x));
}
__device__ __forceinline__ float tanh_acc(float x) {
    float t = __expf(-2.0f * fabsf(x));
    float r = (1.0f - t) / (1.0f + t);
    return copysignf(r, x);
}

// packed f32x2 FMA (PTX-only pattern; element-wise fp32 FMA on a 64-bit pair)
__device__ __forceinline__ void ffma2(unsigned long long& d,
                                      unsigned long long a,
                                      unsigned long long b) {
    asm("fma.rn.f32x2 %0, %1, %2, %0;" : "+l"(d) : "l"(a), "l"(b));
}

__device__ __forceinline__ uint4 ldcg_u4(const uint4* p) {
    uint4 v;
    asm volatile("ld.global.cg.v4.u32 {%0,%1,%2,%3}, [%4];"
                 : "=r"(v.x), "=r"(v.y), "=r"(v.z), "=r"(v.w)
                 : "l"(p) : "memory");
    return v;
}
__device__ __forceinline__ void stcg_u2(uint2* p, unsigned a, unsigned b) {
    asm volatile("st.global.cg.v2.u32 [%0], {%1,%2};"
                 :: "l"(p), "r"(a), "r"(b) : "memory");
}

// ======================= Kernel 1: VQ assignment =============================
#define VQ_TOK  32
#define VQ_TILE 32
#define VQ_PAD  260
#define VQ_SMEM ((VQ_TOK * VQ_PAD + VQ_TILE * VQ_PAD) * sizeof(float))

__global__ __launch_bounds__(TPB, 2)
void vq_kernel(const float* __restrict__ x, const float* __restrict__ cb) {
    extern __shared__ float sm[];
    float* sx  = sm;
    float* scb = sm + VQ_TOK * VQ_PAD;
    __shared__ float scn[KCB];

    const int tid = threadIdx.x;
    const int t0  = blockIdx.x * VQ_TOK;

    for (int i = tid; i < VQ_TOK * (DIM / 4); i += TPB) {
        int tt = i >> 6, d4 = i & 63;
        float4 v = *(const float4*)&x[(t0 + tt) * DIM + d4 * 4];
        *(float4*)&sx[tt * VQ_PAD + d4 * 4] = v;
    }
    for (int k = tid; k < KCB; k += TPB) {
        float s0 = 0.f, s1 = 0.f, s2 = 0.f, s3 = 0.f;
        const float4* cr = (const float4*)&cb[k * DIM];
        #pragma unroll 8
        for (int d = 0; d < DIM / 4; ++d) {
            float4 v = cr[d];
            s0 = fmaf(v.x, v.x, s0); s1 = fmaf(v.y, v.y, s1);
            s2 = fmaf(v.z, v.z, s2); s3 = fmaf(v.w, v.w, s3);
        }
        scn[k] = (s0 + s1) + (s2 + s3);
    }
    __syncthreads();

    const int tt = tid >> 3;
    const int k0 = tid & 7;
    float best = 3.4e38f;
    int   bidx = 0;

    for (int tile = 0; tile < KCB / VQ_TILE; ++tile) {
        for (int i = tid; i < VQ_TILE * (DIM / 4); i += TPB) {
            int cc = i >> 6, d4 = i & 63;
            float4 v = *(const float4*)&cb[(tile * VQ_TILE + cc) * DIM + d4 * 4];
            *(float4*)&scb[cc * VQ_PAD + d4 * 4] = v;
        }
        __syncthreads();
        for (int c = k0; c < VQ_TILE; c += 8) {
            float a0 = 0.f, a1 = 0.f, a2 = 0.f, a3 = 0.f;
            const float* xr = &sx[tt * VQ_PAD];
            const float* cr = &scb[c * VQ_PAD];
            #pragma unroll
            for (int d = 0; d < DIM; d += 4) {
                float4 xv = *(const float4*)&xr[d];
                float4 cv = *(const float4*)&cr[d];
                a0 = fmaf(xv.x, cv.x, a0); a1 = fmaf(xv.y, cv.y, a1);
                a2 = fmaf(xv.z, cv.z, a2); a3 = fmaf(xv.w, cv.w, a3);
            }
            int   kk   = tile * VQ_TILE + c;
            float dist = scn[kk] - 2.0f * ((a0 + a1) + (a2 + a3));
            if (dist < best) { best = dist; bidx = kk; }
        }
        __syncthreads();
    }
    #pragma unroll
    for (int off = 4; off > 0; off >>= 1) {
        float ob = __shfl_down_sync(0xffffffffu, best, off, 8);
        int   oi = __shfl_down_sync(0xffffffffu, bidx, off, 8);
        if (ob < best || (ob == best && oi < bidx)) { best = ob; bidx = oi; }
    }
    if (k0 == 0) g_idx[t0 + tt] = bidx;
}

// ======================= Kernel 1b: prep (W_ih transpose + gen bump) =========
// g_wih_t[k*4096 + b*32 + w*4 + p] = W_ih[(p*HID + b*8 + w)*KCB + k]
// so the gate lane of (cta b, warp w) reads its 4 gate inputs as one float4.
__global__ __launch_bounds__(256)
void prep_kernel(const float* __restrict__ W_ih) {
    int gid = blockIdx.x * 256 + threadIdx.x;       // 0 .. 512*4096-1
    if (gid == 0) g_run = g_run + 1;
    int k = gid >> 12;
    int c = gid & 4095;
    int b = c >> 5, w = (c >> 2) & 7, p = c & 3;
    int rowg = p * HID + b * UPC + w;
    g_wih_t[gid] = __ldg(&W_ih[rowg * KCB + k]);
}

// ======================= Kernel 2: persistent data-flow LSTM =================
// 128 CTAs x 256 threads, all co-resident. Warp w owns ALL FOUR gate rows of
// hidden unit (b*8 + w): {w, 8+w, 16+w, 24+w}. After its in-warp reduce,
// lane 0 has every gate sum -> computes activations and publishes immediately
// (no second __syncthreads, no smem gate round-trip). The poll for the next
// step's h runs at the loop TAIL into a double-buffered smem stage, overlapping
// the gate chain and producer skew. One __syncthreads per step.
#define SH_STRIDE 36   // 32 + 4 pad floats -> conflict-free lane-strided reads

__global__ __launch_bounds__(TPB, 1)
void lstm_kernel(const float* __restrict__ h0,   const float* __restrict__ c0,
                 const float* __restrict__ W_hh,
                 const float* __restrict__ b_ih, const float* __restrict__ b_hh)
{
    __shared__ float shb[2][32 * SH_STRIDE];

    const int tid  = threadIdx.x;
    const int b    = blockIdx.x;
    const int w    = tid >> 5;                // warp -> hidden unit b*8+w
    const int l    = tid & 31;                // lane -> h slice [32l, 32l+32)
    const unsigned gen = g_run;

    // --- one-time: weights into registers as packed f32x2 pairs --------------
    // row p of this warp = gate p of unit (b*8+w)
    unsigned long long wp[4][16];
    #pragma unroll
    for (int p = 0; p < 4; ++p) {
        int rowg = p * HID + b * UPC + w;
        const ulonglong2* wr = (const ulonglong2*)&W_hh[rowg * HID + l * 32];
        #pragma unroll
        for (int q = 0; q < 8; ++q) {
            ulonglong2 v = wr[q];
            wp[p][2 * q]     = v.x;
            wp[p][2 * q + 1] = v.y;
        }
    }
    float bias0 = 0.f, bias1 = 0.f, bias2 = 0.f, bias3 = 0.f;
    float c_state = 0.0f;
    float4 xw4 = make_float4(0.f, 0.f, 0.f, 0.f);
    if (l == 0) {
        int u = b * UPC + w;
        bias0 = b_ih[u]            + b_hh[u];
        bias1 = b_ih[HID + u]      + b_hh[HID + u];
        bias2 = b_ih[2 * HID + u]  + b_hh[2 * HID + u];
        bias3 = b_ih[3 * HID + u]  + b_hh[3 * HID + u];
        c_state = c0[u];
        int idx0 = __ldg(&g_idx[0]);
        xw4 = *(const float4*)&g_wih_t[idx0 * (4 * HID) + b * 32 + w * 4];
    }
    // stage h0 into buffer 0
    {
        float4 hv = *(const float4*)&h0[tid * 4];
        *(float4*)&shb[0][(tid >> 3) * SH_STRIDE + (tid & 7) * 4] = hv;
    }

    for (int step = 1; step <= SEQ; ++step) {
        __syncthreads();     // staging of shb[(step-1)&1] complete

        // ---- register-resident GEMV (identical arithmetic to R5) ------------
        const float* sh = shb[(step - 1) & 1];
        unsigned long long acc[4] = {0ull, 0ull, 0ull, 0ull};
        const ulonglong2* hp = (const ulonglong2*)&sh[l * SH_STRIDE];
        #pragma unroll
        for (int q = 0; q < 8; ++q) {
            ulonglong2 h2 = hp[q];
            #pragma unroll
            for (int p = 0; p < 4; ++p) {
                ffma2(acc[p], wp[p][2 * q],     h2.x);
                ffma2(acc[p], wp[p][2 * q + 1], h2.y);
            }
        }
        float accf[4];
        #pragma unroll
        for (int p = 0; p < 4; ++p) {
            float lo, hi;
            asm("mov.b64 {%0,%1}, %2;" : "=f"(lo), "=f"(hi) : "l"(acc[p]));
            accf[p] = lo + hi;
        }
        #pragma unroll
        for (int off = 16; off > 0; off >>= 1) {
            #pragma unroll
            for (int p = 0; p < 4; ++p)
                accf[p] += __shfl_down_sync(0xffffffffu, accf[p], off);
        }

        // ---- gates + publish: lane 0 has all four gate sums for its unit ----
        if (l == 0) {
            float gi = accf[0] + xw4.x + bias0;
            float gf = accf[1] + xw4.y + bias1;
            float gg = accf[2] + xw4.z + bias2;
            float go = accf[3] + xw4.w + bias3;
            float iv = sigm(gi), fv = sigm(gf);
            float gv = tanh_acc(gg), ov = sigm(go);
            c_state = fv * c_state + iv * gv;
            float hval = ov * tanh_acc(c_state);
            stcg_u2(&g_hpub[step * HID + b * UPC + w],
                    __float_as_uint(hval), gen);
        }

        // ---- tail: prefetch next x-input, poll h(step) into other buffer ----
        if (step < SEQ) {
            float4 nxw;
            if (l == 0) {
                int nidx = __ldg(&g_idx[step]);
                nxw = *(const float4*)&g_wih_t[nidx * (4 * HID) + b * 32 + w * 4];
            }
            const uint4* pa = (const uint4*)&g_hpub[step * HID + tid * 4];
            uint4 A, B;
            for (;;) {
                A = ldcg_u4(pa);
                B = ldcg_u4(pa + 1);
                if ((((A.y ^ gen) | (A.w ^ gen)) |
                     ((B.y ^ gen) | (B.w ^ gen))) == 0u) break;
            }
            float4 hv;
            hv.x = __uint_as_float(A.x); hv.y = __uint_as_float(A.z);
            hv.z = __uint_as_float(B.x); hv.w = __uint_as_float(B.z);
            *(float4*)&shb[step & 1][(tid >> 3) * SH_STRIDE + (tid & 7) * 4] = hv;
            if (l == 0) xw4 = nxw;
        }
    }
}

// ======================= Kernel 3: classifier head ===========================
__global__ __launch_bounds__(256)
void out_kernel(const float* __restrict__ W_out, const float* __restrict__ b_out,
                float* __restrict__ out)
{
    __shared__ float sl[NCLS];
    __shared__ float s_lse;
    const int tid = threadIdx.x, wp_ = tid >> 5, lane = tid & 31;

    for (int ll = wp_; ll < NCLS; ll += 8) {
        float s = 0.0f;
        #pragma unroll 8
        for (int j = lane; j < HID; j += 32) {
            float hv = __uint_as_float(g_hpub[SEQ * HID + j].x);
            s = fmaf(hv, W_out[ll * HID + j], s);
        }
        #pragma unroll
        for (int off = 16; off > 0; off >>= 1)
            s += __shfl_down_sync(0xffffffffu, s, off);
        if (lane == 0) sl[ll] = s + b_out[ll];
    }
    __syncthreads();
    if (tid == 0) {
        float mx = -3.4e38f;
        for (int ll = 0; ll < NCLS; ++ll) mx = fmaxf(mx, sl[ll]);
        float se = 0.0f;
        for (int ll = 0; ll < NCLS; ++ll) se += __expf(sl[ll] - mx);
        s_lse = mx + __logf(se);
    }
    __syncthreads();
    if (tid < NCLS) out[tid] = sl[tid] - s_lse;
}

// ======================= launch ==============================================
extern "C" void kernel_launch(void* const* d_in, const int* in_sizes, int n_in,
                              void* d_out, int out_size) {
    const float* x     = (const float*)d_in[0];
    const float* h0    = (const float*)d_in[1];
    const float* c0    = (const float*)d_in[2];
    const float* cb    = (const float*)d_in[3];
    const float* W_ih  = (const float*)d_in[4];
    const float* W_hh  = (const float*)d_in[5];
    const float* b_ih  = (const float*)d_in[6];
    const float* b_hh  = (const float*)d_in[7];
    const float* W_out = (const float*)d_in[8];
    const float* b_out = (const float*)d_in[9];

    cudaFuncSetAttribute(vq_kernel, cudaFuncAttributeMaxDynamicSharedMemorySize,
                         (int)VQ_SMEM);

    vq_kernel<<<SEQ / VQ_TOK, TPB, VQ_SMEM>>>(x, cb);
    prep_kernel<<<(KCB * 4 * HID) / 256, 256>>>(W_ih);
    lstm_kernel<<<NCTA, TPB>>>(h0, c0, W_hh, b_ih, b_hh);
    out_kernel<<<1, 256>>>(W_out, b_out, (float*)d_out);
}